// round 2
// baseline (speedup 1.0000x reference)
#include <cuda_runtime.h>
#include <cuda_bf16.h>
#include <cstdint>

// Problem constants
#define T_STEPS 2048
#define BATCH   16
#define DIM     1024
#define TBROWS  (T_STEPS*BATCH)   // 32768

constexpr size_t SZ_TBD  = (size_t)T_STEPS * BATCH * DIM;        // 33,554,432
constexpr size_t SZ_T1BD = (size_t)(T_STEPS + 1) * BATCH * DIM;  // 33,570,816

constexpr size_t OUT_OFF   = 0;
constexpr size_t LOGH_OFF  = SZ_TBD;
constexpr size_t SIGNH_OFF = SZ_TBD + SZ_T1BD;
constexpr size_t HLIN_OFF  = SZ_TBD + 2 * SZ_T1BD;               // total 134,250,496

// Scratch (no cudaMalloc allowed): precomputed GEMM results + h broadcast ping-pong
__device__ float g_A[SZ_TBD];   // x @ W_x^T + b
__device__ float g_G[SZ_TBD];   // x @ W_delta^T + b_delta
__device__ float g_hf[2][BATCH * DIM];   // fp32 h broadcast (sign fidelity!)
__device__ unsigned g_arrive;
__device__ volatile unsigned g_release;

// ---------------------------------------------------------------------------
// Init: reset barrier state, zero h0 broadcast, write log_h[0]/sign_h[0] rows
// ---------------------------------------------------------------------------
__global__ void init_kernel(float* __restrict__ d_out) {
    int tid = blockIdx.x * blockDim.x + threadIdx.x;
    if (tid == 0) { g_arrive = 0u; g_release = 0u; }
    const int n = BATCH * DIM;
    for (int i = tid; i < n; i += gridDim.x * blockDim.x) {
        g_hf[0][i] = 0.0f;
        d_out[LOGH_OFF  + i] = -1e4f;   // LOG_ZERO
        d_out[SIGNH_OFF + i] = 1.0f;
    }
}

// ---------------------------------------------------------------------------
// fp32 SIMT GEMM:  C[m][n] = sum_k X[m][k] * W[n][k] + bias[n]
// M=32768, N=1024, K=1024.  Block tile 128x128, BK=16, 256 thr, 8x8 microtile.
// which==0 -> writes g_A, which==1 -> writes g_G
// ---------------------------------------------------------------------------
#define BM 128
#define BN 128
#define BK 16

__global__ __launch_bounds__(256, 2)
void gemm_nt_kernel(const float* __restrict__ X, const float* __restrict__ W,
                    const float* __restrict__ bias, int which)
{
    __shared__ float As[BK][BM + 4];
    __shared__ float Bs[BK][BN + 4];

    const int nb = blockIdx.x;   // 0..7
    const int mb = blockIdx.y;   // 0..255
    const int tid = threadIdx.x;

    const int lr = tid >> 2;          // 0..63
    const int lc = (tid & 3) * 4;     // 0,4,8,12

    const float* Xp = X + (size_t)(mb * BM) * DIM;
    const float* Wp = W + (size_t)(nb * BN) * DIM;

    const int tm = (tid >> 4) * 8;    // 0..120
    const int tn = (tid & 15) * 8;    // 0..120

    float acc[8][8];
#pragma unroll
    for (int i = 0; i < 8; i++)
#pragma unroll
        for (int j = 0; j < 8; j++) acc[i][j] = 0.0f;

    float4 xr0, xr1, wr0, wr1;

    // prologue: load tile 0
    xr0 = *(const float4*)&Xp[(size_t)lr * DIM + lc];
    xr1 = *(const float4*)&Xp[(size_t)(lr + 64) * DIM + lc];
    wr0 = *(const float4*)&Wp[(size_t)lr * DIM + lc];
    wr1 = *(const float4*)&Wp[(size_t)(lr + 64) * DIM + lc];

    As[lc + 0][lr] = xr0.x; As[lc + 1][lr] = xr0.y; As[lc + 2][lr] = xr0.z; As[lc + 3][lr] = xr0.w;
    As[lc + 0][lr + 64] = xr1.x; As[lc + 1][lr + 64] = xr1.y; As[lc + 2][lr + 64] = xr1.z; As[lc + 3][lr + 64] = xr1.w;
    Bs[lc + 0][lr] = wr0.x; Bs[lc + 1][lr] = wr0.y; Bs[lc + 2][lr] = wr0.z; Bs[lc + 3][lr] = wr0.w;
    Bs[lc + 0][lr + 64] = wr1.x; Bs[lc + 1][lr + 64] = wr1.y; Bs[lc + 2][lr + 64] = wr1.z; Bs[lc + 3][lr + 64] = wr1.w;
    __syncthreads();

    const int NKT = DIM / BK;  // 64
    for (int kt = 0; kt < NKT; kt++) {
        if (kt < NKT - 1) {
            int k0 = (kt + 1) * BK;
            xr0 = *(const float4*)&Xp[(size_t)lr * DIM + k0 + lc];
            xr1 = *(const float4*)&Xp[(size_t)(lr + 64) * DIM + k0 + lc];
            wr0 = *(const float4*)&Wp[(size_t)lr * DIM + k0 + lc];
            wr1 = *(const float4*)&Wp[(size_t)(lr + 64) * DIM + k0 + lc];
        }
#pragma unroll
        for (int kk = 0; kk < BK; kk++) {
            float rm[8], rn[8];
            *(float4*)&rm[0] = *(const float4*)&As[kk][tm];
            *(float4*)&rm[4] = *(const float4*)&As[kk][tm + 4];
            *(float4*)&rn[0] = *(const float4*)&Bs[kk][tn];
            *(float4*)&rn[4] = *(const float4*)&Bs[kk][tn + 4];
#pragma unroll
            for (int i = 0; i < 8; i++)
#pragma unroll
                for (int j = 0; j < 8; j++)
                    acc[i][j] += rm[i] * rn[j];
        }
        __syncthreads();
        if (kt < NKT - 1) {
            As[lc + 0][lr] = xr0.x; As[lc + 1][lr] = xr0.y; As[lc + 2][lr] = xr0.z; As[lc + 3][lr] = xr0.w;
            As[lc + 0][lr + 64] = xr1.x; As[lc + 1][lr + 64] = xr1.y; As[lc + 2][lr + 64] = xr1.z; As[lc + 3][lr + 64] = xr1.w;
            Bs[lc + 0][lr] = wr0.x; Bs[lc + 1][lr] = wr0.y; Bs[lc + 2][lr] = wr0.z; Bs[lc + 3][lr] = wr0.w;
            Bs[lc + 0][lr + 64] = wr1.x; Bs[lc + 1][lr + 64] = wr1.y; Bs[lc + 2][lr + 64] = wr1.z; Bs[lc + 3][lr + 64] = wr1.w;
            __syncthreads();
        }
    }

    float* C = which ? g_G : g_A;
    float rb[8];
#pragma unroll
    for (int j = 0; j < 8; j++) rb[j] = bias[nb * BN + tn + j];

#pragma unroll
    for (int i = 0; i < 8; i++) {
        size_t row = (size_t)(mb * BM + tm + i);
        float4 v0, v1;
        v0.x = acc[i][0] + rb[0]; v0.y = acc[i][1] + rb[1];
        v0.z = acc[i][2] + rb[2]; v0.w = acc[i][3] + rb[3];
        v1.x = acc[i][4] + rb[4]; v1.y = acc[i][5] + rb[5];
        v1.z = acc[i][6] + rb[6]; v1.w = acc[i][7] + rb[7];
        *(float4*)&C[row * DIM + nb * BN + tn]     = v0;
        *(float4*)&C[row * DIM + nb * BN + tn + 4] = v1;
    }
}

// ---------------------------------------------------------------------------
// Persistent recurrent kernel: 128 CTAs x 256 threads, one grid barrier/step.
// CTA c owns output columns d in [c*8, c*8+8).  R_h slice resident in SMEM.
// h broadcast in fp32 via L2 (exact — protects sign(h) near zero).
// Warp w handles (b-block bb=w&3, d-block dd=w>>2); lane = K-split (4 k's/lane).
// ---------------------------------------------------------------------------
#define RCTAS 128
#define CPC   8   // columns per CTA

__global__ __launch_bounds__(256, 1)
void recurrent_kernel(const float* __restrict__ x, const float* __restrict__ Rh,
                      const float* __restrict__ b_gate, float* __restrict__ d_out)
{
    extern __shared__ float sm[];
    float* hs = sm;                  // [BATCH][DIM] fp32 = 64 KB
    float* Rs = sm + BATCH * DIM;    // [CPC][DIM]  fp32 = 32 KB

    const int cta  = blockIdx.x;
    const int tid  = threadIdx.x;
    const int lane = tid & 31;
    const int warp = tid >> 5;
    const int bb = warp & 3;   // 0..3 -> b base bb*4
    const int dd = warp >> 2;  // 0..1 -> local d base dd*4

    // Load R_h slice into SMEM (once)
    {
        const float4* src = (const float4*)(Rh + (size_t)cta * CPC * DIM);
        float4* dst = (float4*)Rs;
        for (int i = tid; i < CPC * DIM / 4; i += 256) dst[i] = src[i];
    }

    // Epilogue element owned by lanes 0..15 of each warp
    const int ep_bi = lane >> 2;          // valid for lane<16
    const int ep_di = lane & 3;
    const int ep_b  = bb * 4 + ep_bi;
    const int ep_d  = cta * CPC + dd * 4 + ep_di;
    float bg = (lane < 16) ? b_gate[ep_d] : 0.0f;
    float hprev = 0.0f;

    __syncthreads();  // Rs ready

    for (int t = 0; t < T_STEPS; t++) {
        const int cur = t & 1, nxt = cur ^ 1;

        // --- load h broadcast (fp32, L2-coherent via ld.cg) into SMEM ---
        {
            const float4* src = (const float4*)g_hf[cur];
            float4* dst = (float4*)hs;
#pragma unroll 4
            for (int i = tid; i < (BATCH * DIM) / 4; i += 256) {  // 4096 float4
                dst[i] = __ldcg(src + i);
            }
        }
        __syncthreads();

        // --- recurrent dot: acc[bi][di] = sum_k h[bb*4+bi][k] * R[dd*4+di][k]
        float acc[4][4];
#pragma unroll
        for (int i = 0; i < 4; i++)
#pragma unroll
            for (int j = 0; j < 4; j++) acc[i][j] = 0.0f;

#pragma unroll
        for (int u = 0; u < 8; u++) {
            const int k = u * 128 + lane * 4;
            float4 hv[4], rv[4];
#pragma unroll
            for (int i = 0; i < 4; i++) hv[i] = *(const float4*)&hs[(bb * 4 + i) * DIM + k];
#pragma unroll
            for (int j = 0; j < 4; j++) rv[j] = *(const float4*)&Rs[(dd * 4 + j) * DIM + k];
#pragma unroll
            for (int i = 0; i < 4; i++)
#pragma unroll
                for (int j = 0; j < 4; j++) {
                    acc[i][j] += hv[i].x * rv[j].x;
                    acc[i][j] += hv[i].y * rv[j].y;
                    acc[i][j] += hv[i].z * rv[j].z;
                    acc[i][j] += hv[i].w * rv[j].w;
                }
        }

        // --- warp butterfly reduce over the 32-way K split ---
#pragma unroll
        for (int off = 16; off > 0; off >>= 1)
#pragma unroll
            for (int i = 0; i < 4; i++)
#pragma unroll
                for (int j = 0; j < 4; j++)
                    acc[i][j] += __shfl_xor_sync(0xffffffffu, acc[i][j], off);

        float dot = 0.0f;
#pragma unroll
        for (int i = 0; i < 4; i++)
#pragma unroll
            for (int j = 0; j < 4; j++)
                if (lane == i * 4 + j) dot = acc[i][j];

        // --- elementwise cell epilogue (lanes 0..15 own one (b,d) each) ---
        if (lane < 16) {
            const size_t idx = ((size_t)t * BATCH + ep_b) * DIM + ep_d;
            float v     = g_A[idx] + dot;
            float cand  = tanhf(v);
            float gp    = g_G[idx];
            float delta = 1.0f / (1.0f + expf(-gp));
            float hn    = (1.0f - delta) * hprev + delta * cand;
            float lg    = logf(fabsf(hn) + 1e-12f);
            float sg    = (hn >= 0.0f) ? 1.0f : -1.0f;
            float xv    = __ldg(&x[idx]);
            float z     = hn + xv + bg;
            float sig   = 1.0f / (1.0f + expf(-z));
            float outv  = hn * (z * sig);

            d_out[OUT_OFF + idx]                         = outv;
            d_out[LOGH_OFF + idx + (size_t)BATCH * DIM]  = lg;   // row t+1
            d_out[SIGNH_OFF + idx + (size_t)BATCH * DIM] = sg;   // row t+1
            d_out[HLIN_OFF + idx]                        = hn;

            __stcg(&g_hf[nxt][ep_b * DIM + ep_d], hn);
            hprev = hn;
        }

        // --- grid barrier (release h writes, then arrive + flag wait) ---
        __threadfence();
        __syncthreads();
        if (tid == 0) {
            unsigned tgt = (unsigned)(t + 1) * RCTAS;
            unsigned old = atomicAdd(&g_arrive, 1u);
            if (old == tgt - 1u) {
                g_release = (unsigned)(t + 1);   // volatile store -> L2
            } else {
                while (g_release < (unsigned)(t + 1)) { }
            }
        }
        __syncthreads();
    }
}

// ---------------------------------------------------------------------------
extern "C" void kernel_launch(void* const* d_in, const int* in_sizes, int n_in,
                              void* d_out, int out_size)
{
    const float* x       = (const float*)d_in[0];
    const float* W_x     = (const float*)d_in[1];
    const float* R_h     = (const float*)d_in[2];
    const float* W_delta = (const float*)d_in[3];
    const float* b       = (const float*)d_in[4];
    const float* b_delta = (const float*)d_in[5];
    const float* b_gate  = (const float*)d_in[6];
    float* out = (float*)d_out;

    const int smem_rec = (BATCH * DIM + CPC * DIM) * (int)sizeof(float);  // 98304
    cudaFuncSetAttribute(recurrent_kernel,
                         cudaFuncAttributeMaxDynamicSharedMemorySize, smem_rec);

    init_kernel<<<64, 256>>>(out);
    gemm_nt_kernel<<<dim3(8, TBROWS / BM), 256>>>(x, W_x, b, 0);
    gemm_nt_kernel<<<dim3(8, TBROWS / BM), 256>>>(x, W_delta, b_delta, 1);
    recurrent_kernel<<<RCTAS, 256, smem_rec>>>(x, R_h, b_gate, out);
}

// round 3
// speedup vs baseline: 1.2549x; 1.2549x over previous
#include <cuda_runtime.h>
#include <cuda_bf16.h>
#include <cstdint>

// Problem constants
#define T_STEPS 2048
#define BATCH   16
#define DIM     1024
#define TBROWS  (T_STEPS*BATCH)   // 32768

constexpr size_t SZ_TBD  = (size_t)T_STEPS * BATCH * DIM;        // 33,554,432
constexpr size_t SZ_T1BD = (size_t)(T_STEPS + 1) * BATCH * DIM;  // 33,570,816

constexpr size_t OUT_OFF   = 0;
constexpr size_t LOGH_OFF  = SZ_TBD;
constexpr size_t SIGNH_OFF = SZ_TBD + SZ_T1BD;
constexpr size_t HLIN_OFF  = SZ_TBD + 2 * SZ_T1BD;               // total 134,250,496

// Scratch: precomputed GEMM results + h broadcast ping-pong + barrier state
__device__ float g_A[SZ_TBD];   // x @ W_x^T + b
__device__ float g_G[SZ_TBD];   // x @ W_delta^T + b_delta
__device__ float g_hf[2][BATCH * DIM];   // fp32 h broadcast
__device__ unsigned g_arrive;
__device__ unsigned g_release;

// ---- release/acquire grid-barrier primitives (CG grid.sync pattern) ------
__device__ __forceinline__ unsigned atom_add_acqrel_gpu(unsigned* p, unsigned v) {
    unsigned old;
    asm volatile("atom.acq_rel.gpu.global.add.u32 %0, [%1], %2;"
                 : "=r"(old) : "l"(p), "r"(v) : "memory");
    return old;
}
__device__ __forceinline__ void st_release_gpu(unsigned* p, unsigned v) {
    asm volatile("st.release.gpu.global.u32 [%0], %1;" :: "l"(p), "r"(v) : "memory");
}
__device__ __forceinline__ unsigned ld_acquire_gpu(const unsigned* p) {
    unsigned v;
    asm volatile("ld.acquire.gpu.global.u32 %0, [%1];" : "=r"(v) : "l"(p) : "memory");
    return v;
}

// ---------------------------------------------------------------------------
// Init: reset barrier state, zero h0 broadcast, write log_h[0]/sign_h[0] rows
// ---------------------------------------------------------------------------
__global__ void init_kernel(float* __restrict__ d_out) {
    int tid = blockIdx.x * blockDim.x + threadIdx.x;
    if (tid == 0) { g_arrive = 0u; g_release = 0u; }
    const int n = BATCH * DIM;
    for (int i = tid; i < n; i += gridDim.x * blockDim.x) {
        g_hf[0][i] = 0.0f;
        d_out[LOGH_OFF  + i] = -1e4f;   // LOG_ZERO
        d_out[SIGNH_OFF + i] = 1.0f;
    }
}

// ---------------------------------------------------------------------------
// fp32 SIMT GEMM:  C[m][n] = sum_k X[m][k] * W[n][k] + bias[n]
// M=32768, N=1024, K=1024.  Block tile 128x128, BK=16, 256 thr, 8x8 microtile.
// ---------------------------------------------------------------------------
#define BM 128
#define BN 128
#define BK 16

__global__ __launch_bounds__(256, 2)
void gemm_nt_kernel(const float* __restrict__ X, const float* __restrict__ W,
                    const float* __restrict__ bias, int which)
{
    __shared__ float As[BK][BM + 4];
    __shared__ float Bs[BK][BN + 4];

    const int nb = blockIdx.x;   // 0..7
    const int mb = blockIdx.y;   // 0..255
    const int tid = threadIdx.x;

    const int lr = tid >> 2;          // 0..63
    const int lc = (tid & 3) * 4;     // 0,4,8,12

    const float* Xp = X + (size_t)(mb * BM) * DIM;
    const float* Wp = W + (size_t)(nb * BN) * DIM;

    const int tm = (tid >> 4) * 8;    // 0..120
    const int tn = (tid & 15) * 8;    // 0..120

    float acc[8][8];
#pragma unroll
    for (int i = 0; i < 8; i++)
#pragma unroll
        for (int j = 0; j < 8; j++) acc[i][j] = 0.0f;

    float4 xr0, xr1, wr0, wr1;

    xr0 = *(const float4*)&Xp[(size_t)lr * DIM + lc];
    xr1 = *(const float4*)&Xp[(size_t)(lr + 64) * DIM + lc];
    wr0 = *(const float4*)&Wp[(size_t)lr * DIM + lc];
    wr1 = *(const float4*)&Wp[(size_t)(lr + 64) * DIM + lc];

    As[lc + 0][lr] = xr0.x; As[lc + 1][lr] = xr0.y; As[lc + 2][lr] = xr0.z; As[lc + 3][lr] = xr0.w;
    As[lc + 0][lr + 64] = xr1.x; As[lc + 1][lr + 64] = xr1.y; As[lc + 2][lr + 64] = xr1.z; As[lc + 3][lr + 64] = xr1.w;
    Bs[lc + 0][lr] = wr0.x; Bs[lc + 1][lr] = wr0.y; Bs[lc + 2][lr] = wr0.z; Bs[lc + 3][lr] = wr0.w;
    Bs[lc + 0][lr + 64] = wr1.x; Bs[lc + 1][lr + 64] = wr1.y; Bs[lc + 2][lr + 64] = wr1.z; Bs[lc + 3][lr + 64] = wr1.w;
    __syncthreads();

    const int NKT = DIM / BK;  // 64
    for (int kt = 0; kt < NKT; kt++) {
        if (kt < NKT - 1) {
            int k0 = (kt + 1) * BK;
            xr0 = *(const float4*)&Xp[(size_t)lr * DIM + k0 + lc];
            xr1 = *(const float4*)&Xp[(size_t)(lr + 64) * DIM + k0 + lc];
            wr0 = *(const float4*)&Wp[(size_t)lr * DIM + k0 + lc];
            wr1 = *(const float4*)&Wp[(size_t)(lr + 64) * DIM + k0 + lc];
        }
#pragma unroll
        for (int kk = 0; kk < BK; kk++) {
            float rm[8], rn[8];
            *(float4*)&rm[0] = *(const float4*)&As[kk][tm];
            *(float4*)&rm[4] = *(const float4*)&As[kk][tm + 4];
            *(float4*)&rn[0] = *(const float4*)&Bs[kk][tn];
            *(float4*)&rn[4] = *(const float4*)&Bs[kk][tn + 4];
#pragma unroll
            for (int i = 0; i < 8; i++)
#pragma unroll
                for (int j = 0; j < 8; j++)
                    acc[i][j] += rm[i] * rn[j];
        }
        __syncthreads();
        if (kt < NKT - 1) {
            As[lc + 0][lr] = xr0.x; As[lc + 1][lr] = xr0.y; As[lc + 2][lr] = xr0.z; As[lc + 3][lr] = xr0.w;
            As[lc + 0][lr + 64] = xr1.x; As[lc + 1][lr + 64] = xr1.y; As[lc + 2][lr + 64] = xr1.z; As[lc + 3][lr + 64] = xr1.w;
            Bs[lc + 0][lr] = wr0.x; Bs[lc + 1][lr] = wr0.y; Bs[lc + 2][lr] = wr0.z; Bs[lc + 3][lr] = wr0.w;
            Bs[lc + 0][lr + 64] = wr1.x; Bs[lc + 1][lr + 64] = wr1.y; Bs[lc + 2][lr + 64] = wr1.z; Bs[lc + 3][lr + 64] = wr1.w;
            __syncthreads();
        }
    }

    float* C = which ? g_G : g_A;
    float rb[8];
#pragma unroll
    for (int j = 0; j < 8; j++) rb[j] = bias[nb * BN + tn + j];

#pragma unroll
    for (int i = 0; i < 8; i++) {
        size_t row = (size_t)(mb * BM + tm + i);
        float4 v0, v1;
        v0.x = acc[i][0] + rb[0]; v0.y = acc[i][1] + rb[1];
        v0.z = acc[i][2] + rb[2]; v0.w = acc[i][3] + rb[3];
        v1.x = acc[i][4] + rb[4]; v1.y = acc[i][5] + rb[5];
        v1.z = acc[i][6] + rb[6]; v1.w = acc[i][7] + rb[7];
        *(float4*)&C[row * DIM + nb * BN + tn]     = v0;
        *(float4*)&C[row * DIM + nb * BN + tn + 4] = v1;
    }
}

// ---------------------------------------------------------------------------
// Persistent recurrent kernel: 128 CTAs x 256 threads, one grid barrier/step.
// CTA c owns columns [c*8, c*8+8).  R_h slice lives ENTIRELY IN REGISTERS
// (32 float4/thread), so SMEM traffic per step is h only (128 KB -> 1024 cyc).
// g_A/g_G/x prefetched one step ahead; delta/silu-base precomputed off-chain.
// Reduction: folded shuffle (46 SHFL vs 80). Barrier: acq_rel atomic + release
// flag + acquire poll, with output stores + prefetch inside the wait window.
// ---------------------------------------------------------------------------
#define RCTAS 128
#define CPC   8   // columns per CTA

__global__ __launch_bounds__(256)
void recurrent_kernel(const float* __restrict__ x, const float* __restrict__ Rh,
                      const float* __restrict__ b_gate, float* __restrict__ d_out)
{
    extern __shared__ float hs[];    // [BATCH][DIM] fp32 = 64 KB

    const int cta  = blockIdx.x;
    const int tid  = threadIdx.x;
    const int lane = tid & 31;
    const int warp = tid >> 5;
    const int bb = warp & 3;   // 0..3 -> b base bb*4
    const int dd = warp >> 2;  // 0..1 -> local d base dd*4

    // R_h slice into registers: rreg[j*8+u] = R[(cta*8+dd*4+j)][u*128+lane*4 ..+3]
    float4 rreg[32];
    {
        const float* Rbase = Rh + ((size_t)(cta * CPC + dd * 4)) * DIM + lane * 4;
#pragma unroll
        for (int j = 0; j < 4; j++)
#pragma unroll
            for (int u = 0; u < 8; u++)
                rreg[j * 8 + u] = __ldg((const float4*)(Rbase + (size_t)j * DIM + u * 128));
    }

    // Epilogue element owned by lanes 0..15 of each warp
    const int ep_b = bb * 4 + (lane >> 2);
    const int ep_d = cta * CPC + dd * 4 + (lane & 3);
    const float bg = (lane < 16) ? b_gate[ep_d] : 0.0f;
    float hprev = 0.0f;

    // Prefetch step 0
    float pf_a = 0.f, pf_g = 0.f, pf_x = 0.f;
    if (lane < 16) {
        const size_t idx0 = (size_t)ep_b * DIM + ep_d;
        pf_a = __ldcg(&g_A[idx0]);
        pf_g = __ldcg(&g_G[idx0]);
        pf_x = __ldg(&x[idx0]);
    }

    for (int t = 0; t < T_STEPS; t++) {
        const int cur = t & 1, nxt = cur ^ 1;

        // off-chain precompute from prefetched values
        float delta = 0.f, omdh = 0.f, zbase = 0.f;
        if (lane < 16) {
            delta = 1.0f / (1.0f + expf(-pf_g));
            omdh  = (1.0f - delta) * hprev;
            zbase = pf_x + bg;
        }

        // --- load h broadcast (fp32, L2) into SMEM ---
        {
            const float4* src = (const float4*)g_hf[cur];
            float4* dst = (float4*)hs;
#pragma unroll 4
            for (int i = tid; i < (BATCH * DIM) / 4; i += 256)
                dst[i] = __ldcg(src + i);
        }
        __syncthreads();

        // --- dot: acc[i][j] = sum_k h[bb*4+i][k] * R[dd*4+j][k], K 32-split ---
        float acc[4][4];
#pragma unroll
        for (int i = 0; i < 4; i++)
#pragma unroll
            for (int j = 0; j < 4; j++) acc[i][j] = 0.0f;

#pragma unroll
        for (int u = 0; u < 8; u++) {
            const int k = u * 128 + lane * 4;
            float4 hv[4];
#pragma unroll
            for (int i = 0; i < 4; i++)
                hv[i] = *(const float4*)&hs[(bb * 4 + i) * DIM + k];
#pragma unroll
            for (int i = 0; i < 4; i++)
#pragma unroll
                for (int j = 0; j < 4; j++) {
                    const float4 rv = rreg[j * 8 + u];
                    acc[i][j] += hv[i].x * rv.x;
                    acc[i][j] += hv[i].y * rv.y;
                    acc[i][j] += hv[i].z * rv.z;
                    acc[i][j] += hv[i].w * rv.w;
                }
        }

        // --- folded shuffle reduce: value v=i*4+j lands on lane v (46 SHFL) ---
        float* v16 = &acc[0][0];
#pragma unroll
        for (int v = 0; v < 16; v++) v16[v] += __shfl_xor_sync(0xffffffffu, v16[v], 16);
#pragma unroll
        for (int v = 0; v < 16; v++) v16[v] += __shfl_xor_sync(0xffffffffu, v16[v], 8);
        float v8[8];
#pragma unroll
        for (int j = 0; j < 8; j++) v8[j] = (lane & 8) ? v16[8 + j] : v16[j];
#pragma unroll
        for (int j = 0; j < 8; j++) v8[j] += __shfl_xor_sync(0xffffffffu, v8[j], 4);
        float v4[4];
#pragma unroll
        for (int j = 0; j < 4; j++) v4[j] = (lane & 4) ? v8[4 + j] : v8[j];
#pragma unroll
        for (int j = 0; j < 4; j++) v4[j] += __shfl_xor_sync(0xffffffffu, v4[j], 2);
        float v2[2];
#pragma unroll
        for (int j = 0; j < 2; j++) v2[j] = (lane & 2) ? v4[2 + j] : v4[j];
#pragma unroll
        for (int j = 0; j < 2; j++) v2[j] += __shfl_xor_sync(0xffffffffu, v2[j], 1);
        const float dot = (lane & 1) ? v2[1] : v2[0];

        // --- critical chain: v -> tanh -> h_new -> publish ---
        float hn = 0.0f;
        if (lane < 16) {
            const float v = pf_a + dot;
            const float cand = tanhf(v);
            hn = fmaf(delta, cand, omdh);
            __stcg(&g_hf[nxt][ep_b * DIM + ep_d], hn);
        }
        __syncthreads();

        bool last = false;
        if (tid == 0) {
            unsigned old = atom_add_acqrel_gpu(&g_arrive, 1u);
            if (old == (unsigned)(t + 1) * RCTAS - 1u) {
                st_release_gpu(&g_release, (unsigned)(t + 1));
                last = true;
            }
        }

        // --- off-chain work inside the barrier-wait window ---
        if (lane < 16) {
            const size_t idx = ((size_t)t * BATCH + ep_b) * DIM + ep_d;
            const float lg = logf(fabsf(hn) + 1e-12f);
            const float sg = (hn >= 0.0f) ? 1.0f : -1.0f;
            const float z  = hn + zbase;
            const float sig = 1.0f / (1.0f + expf(-z));
            d_out[OUT_OFF + idx]                         = hn * (z * sig);
            d_out[LOGH_OFF + idx + (size_t)BATCH * DIM]  = lg;
            d_out[SIGNH_OFF + idx + (size_t)BATCH * DIM] = sg;
            d_out[HLIN_OFF + idx]                        = hn;
            hprev = hn;

            const int tn2 = (t + 1 < T_STEPS) ? t + 1 : t;
            const size_t idx2 = ((size_t)tn2 * BATCH + ep_b) * DIM + ep_d;
            pf_a = __ldcg(&g_A[idx2]);
            pf_g = __ldcg(&g_G[idx2]);
            pf_x = __ldg(&x[idx2]);
        }

        if (tid == 0 && !last) {
            while (ld_acquire_gpu(&g_release) < (unsigned)(t + 1)) { }
        }
        __syncthreads();
    }
}

// ---------------------------------------------------------------------------
extern "C" void kernel_launch(void* const* d_in, const int* in_sizes, int n_in,
                              void* d_out, int out_size)
{
    const float* x       = (const float*)d_in[0];
    const float* W_x     = (const float*)d_in[1];
    const float* R_h     = (const float*)d_in[2];
    const float* W_delta = (const float*)d_in[3];
    const float* b       = (const float*)d_in[4];
    const float* b_delta = (const float*)d_in[5];
    const float* b_gate  = (const float*)d_in[6];
    float* out = (float*)d_out;

    const int smem_rec = BATCH * DIM * (int)sizeof(float);  // 65536
    cudaFuncSetAttribute(recurrent_kernel,
                         cudaFuncAttributeMaxDynamicSharedMemorySize, smem_rec);

    init_kernel<<<64, 256>>>(out);
    gemm_nt_kernel<<<dim3(8, TBROWS / BM), 256>>>(x, W_x, b, 0);
    gemm_nt_kernel<<<dim3(8, TBROWS / BM), 256>>>(x, W_delta, b_delta, 1);
    recurrent_kernel<<<RCTAS, 256, smem_rec>>>(x, R_h, b_gate, out);
}

// round 4
// speedup vs baseline: 1.4784x; 1.1781x over previous
#include <cuda_runtime.h>
#include <cuda_bf16.h>
#include <cstdint>

// Problem constants
#define T_STEPS 2048
#define BATCH   16
#define DIM     1024
#define TBROWS  (T_STEPS*BATCH)   // 32768

constexpr size_t SZ_TBD  = (size_t)T_STEPS * BATCH * DIM;        // 33,554,432
constexpr size_t SZ_T1BD = (size_t)(T_STEPS + 1) * BATCH * DIM;  // 33,570,816

constexpr size_t OUT_OFF   = 0;
constexpr size_t LOGH_OFF  = SZ_TBD;
constexpr size_t SIGNH_OFF = SZ_TBD + SZ_T1BD;
constexpr size_t HLIN_OFF  = SZ_TBD + 2 * SZ_T1BD;               // total 134,250,496

#define RCTAS 128
#define CPC   8   // columns per CTA

// Scratch: precomputed GEMM results + h broadcast ping-pong + per-CTA flags
__device__ float g_A[SZ_TBD];   // x @ W_x^T + b
__device__ float g_G[SZ_TBD];   // x @ W_delta^T + b_delta
__device__ float g_hf[2][BATCH * DIM];   // fp32 h broadcast
__device__ unsigned g_flags[RCTAS * 8];  // flag[c] at [c*8], 32B padded

// ---- memory-order primitives --------------------------------------------
__device__ __forceinline__ void st_release_gpu(unsigned* p, unsigned v) {
    asm volatile("st.release.gpu.global.u32 [%0], %1;" :: "l"(p), "r"(v) : "memory");
}
__device__ __forceinline__ unsigned ld_acquire_gpu(const unsigned* p) {
    unsigned v;
    asm volatile("ld.acquire.gpu.global.u32 %0, [%1];" : "=r"(v) : "l"(p) : "memory");
    return v;
}
__device__ __forceinline__ void cp_async16(uint32_t dst, const void* src) {
    asm volatile("cp.async.cg.shared.global [%0], [%1], 16;" :: "r"(dst), "l"(src));
}
__device__ __forceinline__ void cp_async_commit() {
    asm volatile("cp.async.commit_group;");
}
template <int N>
__device__ __forceinline__ void cp_async_wait() {
    asm volatile("cp.async.wait_group %0;" :: "n"(N));
}

// ---------------------------------------------------------------------------
// Init: reset flags, zero h0 broadcast, write log_h[0]/sign_h[0] rows
// ---------------------------------------------------------------------------
__global__ void init_kernel(float* __restrict__ d_out) {
    int tid = blockIdx.x * blockDim.x + threadIdx.x;
    if (tid < RCTAS * 8) g_flags[tid] = 0u;
    const int n = BATCH * DIM;
    for (int i = tid; i < n; i += gridDim.x * blockDim.x) {
        g_hf[0][i] = 0.0f;
        d_out[LOGH_OFF  + i] = -1e4f;   // LOG_ZERO
        d_out[SIGNH_OFF + i] = 1.0f;
    }
}

// ---------------------------------------------------------------------------
// fp32 SIMT GEMM:  C[m][n] = sum_k X[m][k] * W[n][k] + bias[n]
// M=32768, N=1024, K=1024.  Block tile 128x128, BK=16, 256 thr, 8x8 microtile.
// ---------------------------------------------------------------------------
#define BM 128
#define BN 128
#define BK 16

__global__ __launch_bounds__(256, 2)
void gemm_nt_kernel(const float* __restrict__ X, const float* __restrict__ W,
                    const float* __restrict__ bias, int which)
{
    __shared__ float As[BK][BM + 4];
    __shared__ float Bs[BK][BN + 4];

    const int nb = blockIdx.x;   // 0..7
    const int mb = blockIdx.y;   // 0..255
    const int tid = threadIdx.x;

    const int lr = tid >> 2;          // 0..63
    const int lc = (tid & 3) * 4;     // 0,4,8,12

    const float* Xp = X + (size_t)(mb * BM) * DIM;
    const float* Wp = W + (size_t)(nb * BN) * DIM;

    const int tm = (tid >> 4) * 8;    // 0..120
    const int tn = (tid & 15) * 8;    // 0..120

    float acc[8][8];
#pragma unroll
    for (int i = 0; i < 8; i++)
#pragma unroll
        for (int j = 0; j < 8; j++) acc[i][j] = 0.0f;

    float4 xr0, xr1, wr0, wr1;

    xr0 = *(const float4*)&Xp[(size_t)lr * DIM + lc];
    xr1 = *(const float4*)&Xp[(size_t)(lr + 64) * DIM + lc];
    wr0 = *(const float4*)&Wp[(size_t)lr * DIM + lc];
    wr1 = *(const float4*)&Wp[(size_t)(lr + 64) * DIM + lc];

    As[lc + 0][lr] = xr0.x; As[lc + 1][lr] = xr0.y; As[lc + 2][lr] = xr0.z; As[lc + 3][lr] = xr0.w;
    As[lc + 0][lr + 64] = xr1.x; As[lc + 1][lr + 64] = xr1.y; As[lc + 2][lr + 64] = xr1.z; As[lc + 3][lr + 64] = xr1.w;
    Bs[lc + 0][lr] = wr0.x; Bs[lc + 1][lr] = wr0.y; Bs[lc + 2][lr] = wr0.z; Bs[lc + 3][lr] = wr0.w;
    Bs[lc + 0][lr + 64] = wr1.x; Bs[lc + 1][lr + 64] = wr1.y; Bs[lc + 2][lr + 64] = wr1.z; Bs[lc + 3][lr + 64] = wr1.w;
    __syncthreads();

    const int NKT = DIM / BK;  // 64
    for (int kt = 0; kt < NKT; kt++) {
        if (kt < NKT - 1) {
            int k0 = (kt + 1) * BK;
            xr0 = *(const float4*)&Xp[(size_t)lr * DIM + k0 + lc];
            xr1 = *(const float4*)&Xp[(size_t)(lr + 64) * DIM + k0 + lc];
            wr0 = *(const float4*)&Wp[(size_t)lr * DIM + k0 + lc];
            wr1 = *(const float4*)&Wp[(size_t)(lr + 64) * DIM + k0 + lc];
        }
#pragma unroll
        for (int kk = 0; kk < BK; kk++) {
            float rm[8], rn[8];
            *(float4*)&rm[0] = *(const float4*)&As[kk][tm];
            *(float4*)&rm[4] = *(const float4*)&As[kk][tm + 4];
            *(float4*)&rn[0] = *(const float4*)&Bs[kk][tn];
            *(float4*)&rn[4] = *(const float4*)&Bs[kk][tn + 4];
#pragma unroll
            for (int i = 0; i < 8; i++)
#pragma unroll
                for (int j = 0; j < 8; j++)
                    acc[i][j] += rm[i] * rn[j];
        }
        __syncthreads();
        if (kt < NKT - 1) {
            As[lc + 0][lr] = xr0.x; As[lc + 1][lr] = xr0.y; As[lc + 2][lr] = xr0.z; As[lc + 3][lr] = xr0.w;
            As[lc + 0][lr + 64] = xr1.x; As[lc + 1][lr + 64] = xr1.y; As[lc + 2][lr + 64] = xr1.z; As[lc + 3][lr + 64] = xr1.w;
            Bs[lc + 0][lr] = wr0.x; Bs[lc + 1][lr] = wr0.y; Bs[lc + 2][lr] = wr0.z; Bs[lc + 3][lr] = wr0.w;
            Bs[lc + 0][lr + 64] = wr1.x; Bs[lc + 1][lr + 64] = wr1.y; Bs[lc + 2][lr + 64] = wr1.z; Bs[lc + 3][lr + 64] = wr1.w;
            __syncthreads();
        }
    }

    float* C = which ? g_G : g_A;
    float rb[8];
#pragma unroll
    for (int j = 0; j < 8; j++) rb[j] = bias[nb * BN + tn + j];

#pragma unroll
    for (int i = 0; i < 8; i++) {
        size_t row = (size_t)(mb * BM + tm + i);
        float4 v0, v1;
        v0.x = acc[i][0] + rb[0]; v0.y = acc[i][1] + rb[1];
        v0.z = acc[i][2] + rb[2]; v0.w = acc[i][3] + rb[3];
        v1.x = acc[i][4] + rb[4]; v1.y = acc[i][5] + rb[5];
        v1.z = acc[i][6] + rb[6]; v1.w = acc[i][7] + rb[7];
        *(float4*)&C[row * DIM + nb * BN + tn]     = v0;
        *(float4*)&C[row * DIM + nb * BN + tn + 4] = v1;
    }
}

// ---------------------------------------------------------------------------
// Persistent recurrent kernel: 128 CTAs x 256 threads.
// R_h slice in registers.  h broadcast: 4x16KB cp.async chunk-groups
// OVERLAPPED with the dot (wait_group(3-u) staging).  Grid barrier:
// one-hop producer flags (threadfence + st.release flag, ld.acquire poll).
// Safe with 2-buffer ping-pong: flag[c]=t+1 is set only after CTA c finished
// READING h[t], so any write into h[t]'s buffer (at step t+1) is ordered
// behind every CTA's reads of it.
// ---------------------------------------------------------------------------
__global__ __launch_bounds__(256)
void recurrent_kernel(const float* __restrict__ x, const float* __restrict__ Rh,
                      const float* __restrict__ b_gate, float* __restrict__ d_out)
{
    extern __shared__ float hs[];    // [BATCH][DIM] fp32 = 64 KB
    const uint32_t hs_u32 = (uint32_t)__cvta_generic_to_shared(hs);

    const int cta  = blockIdx.x;
    const int tid  = threadIdx.x;
    const int lane = tid & 31;
    const int warp = tid >> 5;
    const int bb = warp & 3;   // 0..3 -> b base bb*4
    const int dd = warp >> 2;  // 0..1 -> local d base dd*4

    // R_h slice into registers: rreg[j*8+u] = R[(cta*8+dd*4+j)][u*128+lane*4 ..+3]
    float4 rreg[32];
    {
        const float* Rbase = Rh + ((size_t)(cta * CPC + dd * 4)) * DIM + lane * 4;
#pragma unroll
        for (int j = 0; j < 4; j++)
#pragma unroll
            for (int u = 0; u < 8; u++)
                rreg[j * 8 + u] = __ldg((const float4*)(Rbase + (size_t)j * DIM + u * 128));
    }

    // Epilogue element owned by lanes 0..15 of each warp
    const int ep_b = bb * 4 + (lane >> 2);
    const int ep_d = cta * CPC + dd * 4 + (lane & 3);
    const float bg = (lane < 16) ? b_gate[ep_d] : 0.0f;
    float hprev = 0.0f;

    // Prefetch step 0
    float pf_a = 0.f, pf_g = 0.f, pf_x = 0.f;
    if (lane < 16) {
        const size_t idx0 = (size_t)ep_b * DIM + ep_d;
        pf_a = __ldcg(&g_A[idx0]);
        pf_g = __ldcg(&g_G[idx0]);
        pf_x = __ldg(&x[idx0]);
    }

    // cp.async chunk source offsets (float4 units); chunk u covers K range
    // [u*256, (u+1)*256) over all 16 rows.  Per chunk: 1024 float4, 4/thread.
    int cp_row[4], cp_c4[4];
#pragma unroll
    for (int j = 0; j < 4; j++) {
        int f = tid + j * 256;
        cp_row[j] = f >> 6;      // 0..15
        cp_c4[j]  = f & 63;      // 0..63
    }

    for (int t = 0; t < T_STEPS; t++) {
        const int cur = t & 1, nxt = cur ^ 1;

        // --- issue h broadcast: 4 chunk-groups of cp.async (16B each) ---
        {
            const float4* src = (const float4*)g_hf[cur];
#pragma unroll
            for (int u = 0; u < 4; u++) {
#pragma unroll
                for (int j = 0; j < 4; j++) {
                    const int off = cp_row[j] * 256 + u * 64 + cp_c4[j];
                    cp_async16(hs_u32 + (uint32_t)off * 16, src + off);
                }
                cp_async_commit();
            }
        }

        // --- off-chain precompute (fills first-chunk latency) ---
        float delta = 0.f, omdh = 0.f, zbase = 0.f;
        if (lane < 16) {
            delta = 1.0f / (1.0f + expf(-pf_g));
            omdh  = (1.0f - delta) * hprev;
            zbase = pf_x + bg;
        }

        // --- dot overlapped with chunk arrival ---
        float acc[4][4];
#pragma unroll
        for (int i = 0; i < 4; i++)
#pragma unroll
            for (int j = 0; j < 4; j++) acc[i][j] = 0.0f;

#pragma unroll
        for (int u = 0; u < 4; u++) {
            if      (u == 0) cp_async_wait<3>();
            else if (u == 1) cp_async_wait<2>();
            else if (u == 2) cp_async_wait<1>();
            else             cp_async_wait<0>();
            __syncthreads();
#pragma unroll
            for (int v = 0; v < 2; v++) {
                const int ur = u * 2 + v;
                const int k  = ur * 128 + lane * 4;
                float4 hv[4];
#pragma unroll
                for (int i = 0; i < 4; i++)
                    hv[i] = *(const float4*)&hs[(bb * 4 + i) * DIM + k];
#pragma unroll
                for (int i = 0; i < 4; i++)
#pragma unroll
                    for (int j = 0; j < 4; j++) {
                        const float4 rv = rreg[j * 8 + ur];
                        acc[i][j] += hv[i].x * rv.x;
                        acc[i][j] += hv[i].y * rv.y;
                        acc[i][j] += hv[i].z * rv.z;
                        acc[i][j] += hv[i].w * rv.w;
                    }
            }
        }

        // --- folded shuffle reduce: value v=i*4+j lands on lane v ---
        float* v16 = &acc[0][0];
#pragma unroll
        for (int v = 0; v < 16; v++) v16[v] += __shfl_xor_sync(0xffffffffu, v16[v], 16);
#pragma unroll
        for (int v = 0; v < 16; v++) v16[v] += __shfl_xor_sync(0xffffffffu, v16[v], 8);
        float v8[8];
#pragma unroll
        for (int j = 0; j < 8; j++) v8[j] = (lane & 8) ? v16[8 + j] : v16[j];
#pragma unroll
        for (int j = 0; j < 8; j++) v8[j] += __shfl_xor_sync(0xffffffffu, v8[j], 4);
        float v4[4];
#pragma unroll
        for (int j = 0; j < 4; j++) v4[j] = (lane & 4) ? v8[4 + j] : v8[j];
#pragma unroll
        for (int j = 0; j < 4; j++) v4[j] += __shfl_xor_sync(0xffffffffu, v4[j], 2);
        float v2[2];
#pragma unroll
        for (int j = 0; j < 2; j++) v2[j] = (lane & 2) ? v4[2 + j] : v4[j];
#pragma unroll
        for (int j = 0; j < 2; j++) v2[j] += __shfl_xor_sync(0xffffffffu, v2[j], 1);
        const float dot = (lane & 1) ? v2[1] : v2[0];

        // --- critical chain: v -> tanh -> h_new -> publish ---
        float hn = 0.0f;
        if (lane < 16) {
            const float v = pf_a + dot;
            const float cand = tanhf(v);
            hn = fmaf(delta, cand, omdh);
            __stcg(&g_hf[nxt][ep_b * DIM + ep_d], hn);
            __threadfence();   // make h visible at gpu scope before flag
        }
        __syncthreads();
        if (tid == 0) st_release_gpu(&g_flags[cta * 8], (unsigned)(t + 1));

        // --- off-chain work inside the barrier-wait window ---
        if (lane < 16) {
            const size_t idx = ((size_t)t * BATCH + ep_b) * DIM + ep_d;
            const float lg = logf(fabsf(hn) + 1e-12f);
            const float sg = (hn >= 0.0f) ? 1.0f : -1.0f;
            const float z  = hn + zbase;
            const float sig = 1.0f / (1.0f + expf(-z));
            d_out[OUT_OFF + idx]                         = hn * (z * sig);
            d_out[LOGH_OFF + idx + (size_t)BATCH * DIM]  = lg;
            d_out[SIGNH_OFF + idx + (size_t)BATCH * DIM] = sg;
            d_out[HLIN_OFF + idx]                        = hn;
            hprev = hn;

            const int tn2 = (t + 1 < T_STEPS) ? t + 1 : t;
            const size_t idx2 = ((size_t)tn2 * BATCH + ep_b) * DIM + ep_d;
            pf_a = __ldcg(&g_A[idx2]);
            pf_g = __ldcg(&g_G[idx2]);
            pf_x = __ldg(&x[idx2]);
        }

        // --- one-hop barrier: poll all 128 producer flags ---
        if (tid < RCTAS) {
            while (ld_acquire_gpu(&g_flags[tid * 8]) < (unsigned)(t + 1)) { }
        }
        __syncthreads();
    }
}

// ---------------------------------------------------------------------------
extern "C" void kernel_launch(void* const* d_in, const int* in_sizes, int n_in,
                              void* d_out, int out_size)
{
    const float* x       = (const float*)d_in[0];
    const float* W_x     = (const float*)d_in[1];
    const float* R_h     = (const float*)d_in[2];
    const float* W_delta = (const float*)d_in[3];
    const float* b       = (const float*)d_in[4];
    const float* b_delta = (const float*)d_in[5];
    const float* b_gate  = (const float*)d_in[6];
    float* out = (float*)d_out;

    const int smem_rec = BATCH * DIM * (int)sizeof(float);  // 65536
    cudaFuncSetAttribute(recurrent_kernel,
                         cudaFuncAttributeMaxDynamicSharedMemorySize, smem_rec);

    init_kernel<<<64, 256>>>(out);
    gemm_nt_kernel<<<dim3(8, TBROWS / BM), 256>>>(x, W_x, b, 0);
    gemm_nt_kernel<<<dim3(8, TBROWS / BM), 256>>>(x, W_delta, b_delta, 1);
    recurrent_kernel<<<RCTAS, 256, smem_rec>>>(x, R_h, b_gate, out);
}